// round 14
// baseline (speedup 1.0000x reference)
#include <cuda_runtime.h>
#include <cuda_bf16.h>
#include <math.h>
#include <stdint.h>

// Problem constants
#define NSP   8192          // D*H*W = 8*32*32
#define CIN   256
#define K27   27
#define CK    6912          // CIN * 27
#define DD    8
#define HH    32
#define WW    32

typedef unsigned long long ull;

// Scratch (allocation-free rule: __device__ globals)
__device__ float g_d[108 * NSP];                    // offset-conv output
__device__ float g_h[2][CIN * NSP];                 // hidden ping-pong
__device__ float g_dp[2][108 * NSP];                // split-K partials (offset conv)
__device__ float g_zerobias[256];                   // zero bias for partial passes
__device__ __nv_bfloat16 g_Shi[(size_t)CK * NSP];   // im2col/sampled matrix hi limb
__device__ __nv_bfloat16 g_Slo[(size_t)CK * NSP];   // im2col/sampled matrix lo limb
__device__ __nv_bfloat16 g_Whi[(size_t)CIN * CK];   // main weights hi limb
__device__ __nv_bfloat16 g_Wlo[(size_t)CIN * CK];   // main weights lo limb
__device__ __nv_bfloat16 g_OWhi[(size_t)128 * CK];  // offset weights hi (padded to 128 rows)
__device__ __nv_bfloat16 g_OWlo[(size_t)128 * CK];  // offset weights lo

// ===========================================================================
// PTX helpers
// ===========================================================================
__device__ __forceinline__ uint32_t smem_u32(const void* p) {
    uint32_t a;
    asm("{ .reg .u64 t; cvta.to.shared.u64 t, %1; cvt.u32.u64 %0, t; }" : "=r"(a) : "l"(p));
    return a;
}
__device__ __forceinline__ void cp16(uint32_t dst, const void* src) {
    asm volatile("cp.async.cg.shared.global [%0], [%1], 16;" :: "r"(dst), "l"(src));
}
__device__ __forceinline__ void cp_commit() {
    asm volatile("cp.async.commit_group;" ::: "memory");
}
template <int N>
__device__ __forceinline__ void cp_wait() {
    asm volatile("cp.async.wait_group %0;" :: "n"(N) : "memory");
}
__device__ __forceinline__ void ldsm4(uint32_t* r, uint32_t addr) {
    asm volatile("ldmatrix.sync.aligned.m8n8.x4.shared.b16 {%0,%1,%2,%3}, [%4];"
                 : "=r"(r[0]), "=r"(r[1]), "=r"(r[2]), "=r"(r[3]) : "r"(addr));
}
__device__ __forceinline__ void ldsm4t(uint32_t* r, uint32_t addr) {
    asm volatile("ldmatrix.sync.aligned.m8n8.x4.trans.shared.b16 {%0,%1,%2,%3}, [%4];"
                 : "=r"(r[0]), "=r"(r[1]), "=r"(r[2]), "=r"(r[3]) : "r"(addr));
}
__device__ __forceinline__ void mma_bf16(float* d, const uint32_t* a, uint32_t b0, uint32_t b1) {
    asm volatile("mma.sync.aligned.m16n8k16.row.col.f32.bf16.bf16.f32 "
                 "{%0,%1,%2,%3}, {%4,%5,%6,%7}, {%8,%9}, {%0,%1,%2,%3};"
                 : "+f"(d[0]), "+f"(d[1]), "+f"(d[2]), "+f"(d[3])
                 : "r"(a[0]), "r"(a[1]), "r"(a[2]), "r"(a[3]), "r"(b0), "r"(b1));
}

// ===========================================================================
// Weight limb-split: fp32 -> (hi, lo) bf16
// ===========================================================================
__global__ __launch_bounds__(256) void split_kernel(
    const float* __restrict__ src, __nv_bfloat16* __restrict__ hi,
    __nv_bfloat16* __restrict__ lo, int n)
{
    int i = blockIdx.x * 256 + threadIdx.x;
    if (i >= n) return;
    float a = src[i];
    __nv_bfloat16 h = __float2bfloat16(a);
    hi[i] = h;
    lo[i] = __float2bfloat16(a - __bfloat162float(h));
}

// Padded variant: 128 rows, rows >= 108 are zero.
__global__ __launch_bounds__(256) void owsplit_kernel(
    const float* __restrict__ src, __nv_bfloat16* __restrict__ hi,
    __nv_bfloat16* __restrict__ lo)
{
    int i = blockIdx.x * 256 + threadIdx.x;
    if (i >= 128 * CK) return;
    int row = i / CK;
    float a = (row < 108) ? src[i] : 0.0f;
    __nv_bfloat16 h = __float2bfloat16(a);
    hi[i] = h;
    lo[i] = __float2bfloat16(a - __bfloat162float(h));
}

// ===========================================================================
// Fused im2col + limb split for the plain 3x3x3 pad-1 conv
// ===========================================================================
__global__ __launch_bounds__(256) void im2col_split_kernel(
    const float* __restrict__ src,
    __nv_bfloat16* __restrict__ Shi, __nv_bfloat16* __restrict__ Slo)
{
    int p = blockIdx.x * 256 + threadIdx.x;   // grid.x = 32
    int k = blockIdx.y;                        // 27
    int c = blockIdx.z;                        // 256
    int z = p >> 10, y = (p >> 5) & 31, x = p & 31;
    int kd = k / 9, kh = (k / 3) % 3, kw = k % 3;
    int zz = z + kd - 1, yy = y + kh - 1, xx = x + kw - 1;
    float v = 0.0f;
    if ((unsigned)zz < DD && (unsigned)yy < HH && (unsigned)xx < WW)
        v = src[c * NSP + (zz << 10) + (yy << 5) + xx];
    __nv_bfloat16 hv = __float2bfloat16(v);
    size_t o = (size_t)(c * K27 + k) * NSP + p;
    Shi[o] = hv;
    Slo[o] = __float2bfloat16(v - __bfloat162float(hv));
}

// ===========================================================================
// Deformable sampling -> bf16 limb-split S  (S[(c*27+k)][p])
// ===========================================================================
__global__ void sample_kernel(const float* __restrict__ src,
                              const float* __restrict__ dd,
                              __nv_bfloat16* __restrict__ Shi,
                              __nv_bfloat16* __restrict__ Slo) {
    int p = blockIdx.x * 128 + threadIdx.x;   // grid.x = 64
    int k = blockIdx.y;                        // 27
    int z = p >> 10, y = (p >> 5) & 31, x = p & 31;
    int kd = k / 9, kh = (k / 3) % 3, kw = k % 3;

    float cd = (float)(z + kd - 1) + dd[(k * 3 + 0) * NSP + p];
    float ch = (float)(y + kh - 1) + dd[(k * 3 + 1) * NSP + p];
    float cw = (float)(x + kw - 1) + dd[(k * 3 + 2) * NSP + p];
    float m  = 1.0f / (1.0f + expf(-dd[(81 + k) * NSP + p]));

    float d0 = floorf(cd), h0 = floorf(ch), w0 = floorf(cw);
    float fd = cd - d0, fh = ch - h0, fw = cw - w0;
    int z0 = (int)d0, y0 = (int)h0, x0 = (int)w0;

    float wt[8]; int idx[8];
#pragma unroll
    for (int j = 0; j < 8; j++) {
        int dz = (j >> 2) & 1, dy = (j >> 1) & 1, dx = j & 1;
        int zi = z0 + dz, yi = y0 + dy, xi = x0 + dx;
        float w = (dz ? fd : 1.0f - fd) * (dy ? fh : 1.0f - fh) * (dx ? fw : 1.0f - fw);
        bool valid = ((unsigned)zi < DD) && ((unsigned)yi < HH) && ((unsigned)xi < WW);
        wt[j] = valid ? (w * m) : 0.0f;
        int zc = min(max(zi, 0), DD - 1);
        int yc = min(max(yi, 0), HH - 1);
        int xc = min(max(xi, 0), WW - 1);
        idx[j] = (zc << 10) + (yc << 5) + xc;
    }

    size_t base = (size_t)k * NSP + p;
#pragma unroll 4
    for (int c = 0; c < CIN; c++) {
        const float* b = src + c * NSP;
        float acc = wt[0] * b[idx[0]] + wt[1] * b[idx[1]]
                  + wt[2] * b[idx[2]] + wt[3] * b[idx[3]]
                  + wt[4] * b[idx[4]] + wt[5] * b[idx[5]]
                  + wt[6] * b[idx[6]] + wt[7] * b[idx[7]];
        __nv_bfloat16 hv = __float2bfloat16(acc);
        size_t o = base + (size_t)c * K27 * NSP;
        Shi[o] = hv;
        Slo[o] = __float2bfloat16(acc - __bfloat162float(hv));
    }
}

// ===========================================================================
// Tensor-core GEMM (mma.sync bf16, 2-limb split), 3-stage cp.async pipeline.
// Inner tile: ALL 32 ldmatrix fragments (both ks halves) loaded up front,
// then 96 MMAs in limb-major order (8 independent accs between acc reuse).
// ===========================================================================
#define ASZ   (128 * 40 * 2)      // 10240 B per A limb tile
#define BSZ   (32 * 72 * 2)       // 4608 B per B limb tile
#define STAGE (2 * ASZ + 2 * BSZ) // 29696 B
#define NSTAGE 3
#define SMTOT (NSTAGE * STAGE)    // 89088 B

__global__ __launch_bounds__(256, 2) void mma_gemm(
    const __nv_bfloat16* __restrict__ Ahi, const __nv_bfloat16* __restrict__ Alo,
    const __nv_bfloat16* __restrict__ Bhi, const __nv_bfloat16* __restrict__ Blo,
    const float* __restrict__ bias, float* __restrict__ C,
    int M, int nkt, int doRelu, int zStride)
{
    extern __shared__ char smem[];
    uint32_t sb = smem_u32(smem);
    int tid = threadIdx.x;
    int wid = tid >> 5, lid = tid & 31;
    int p0 = blockIdx.x * 64;          // N tile base
    int mBase = blockIdx.y * 128;      // M tile base
    int ktBase = blockIdx.z * nkt;     // K-slice base (in BK=32 units)

    int wm = wid & 3;                  // 0..3 -> 32 rows each
    int wn = wid >> 2;                 // 0..1 -> 32 cols each
    int quad = lid >> 3, rr = lid & 7;

    // loader indices
    int aRow = tid >> 2;               // 0..63 (x2 with +64)
    int aU   = tid & 3;                // 16B unit in 64B row
    int bRow = tid >> 3;               // 0..31
    int bU   = tid & 7;                // 16B unit in 128B row

    float acc[2][4][4];
#pragma unroll
    for (int i = 0; i < 2; i++)
#pragma unroll
        for (int j = 0; j < 4; j++)
#pragma unroll
            for (int q = 0; q < 4; q++) acc[i][j][q] = 0.f;

    // precomputed fragment smem offsets (within a stage)
    uint32_t aOff[2][2], bOff[2][2];   // [ks][mf] / [ks][nb]
#pragma unroll
    for (int ks = 0; ks < 2; ks++) {
#pragma unroll
        for (int mf = 0; mf < 2; mf++) {
            int row = wm * 32 + mf * 16 + ((quad & 1) ? 8 : 0) + rr;
            int col = ks * 16 + ((quad >> 1) ? 8 : 0);
            aOff[ks][mf] = (uint32_t)(row * 40 + col) * 2;
        }
#pragma unroll
        for (int nb = 0; nb < 2; nb++) {
            int row = ks * 16 + ((quad & 1) ? 8 : 0) + rr;
            int col = wn * 32 + nb * 16 + ((quad >> 1) ? 8 : 0);
            bOff[ks][nb] = 2 * ASZ + (uint32_t)(row * 72 + col) * 2;
        }
    }

    auto issue = [&](int st, int kt) {
        uint32_t s = sb + st * STAGE;
        int kOff = (ktBase + kt) * 32;
#pragma unroll
        for (int t = 0; t < 2; t++) {
            int row = aRow + t * 64;
            uint32_t d = s + row * 80 + aU * 16;
            const __nv_bfloat16* sh = Ahi + (size_t)(mBase + row) * CK + kOff + aU * 8;
            const __nv_bfloat16* sl = Alo + (size_t)(mBase + row) * CK + kOff + aU * 8;
            cp16(d, sh);
            cp16(d + ASZ, sl);
        }
        {
            uint32_t d = s + 2 * ASZ + bRow * 144 + bU * 16;
            const __nv_bfloat16* sh = Bhi + (size_t)(kOff + bRow) * NSP + p0 + bU * 8;
            const __nv_bfloat16* sl = Blo + (size_t)(kOff + bRow) * NSP + p0 + bU * 8;
            cp16(d, sh);
            cp16(d + BSZ, sl);
        }
        cp_commit();
    };

    // preload stages 0 and 1
    issue(0, 0);
    if (nkt > 1) issue(1, 1);

    int st = 0;
    for (int kt = 0; kt < nkt; kt++) {
        cp_wait<1>();          // stage for kt has landed
        __syncthreads();       // publish stage kt; fence vs new issue below

        if (kt + 2 < nkt) {
            int nst = st + 2; if (nst >= NSTAGE) nst -= NSTAGE;
            issue(nst, kt + 2);    // writes the stage freed at iteration kt-1
        }

        uint32_t s = sb + st * STAGE;

        // ---- load ALL fragments for both ks halves (32 ldmatrix) ----
        uint32_t ah[2][2][4], al[2][2][4];   // [ks][mf][4]
        uint32_t bh[2][8], bl[2][8];         // [ks][nf*2+reg]
#pragma unroll
        for (int ks = 0; ks < 2; ks++) {
#pragma unroll
            for (int mf = 0; mf < 2; mf++) {
                uint32_t ad = s + aOff[ks][mf];
                ldsm4(ah[ks][mf], ad);
                ldsm4(al[ks][mf], ad + ASZ);
            }
#pragma unroll
            for (int nb = 0; nb < 2; nb++) {
                uint32_t bd = s + bOff[ks][nb];
                uint32_t t[4];
                ldsm4t(t, bd);
                bh[ks][nb * 4 + 0] = t[0]; bh[ks][nb * 4 + 1] = t[1];
                bh[ks][nb * 4 + 2] = t[2]; bh[ks][nb * 4 + 3] = t[3];
                ldsm4t(t, bd + BSZ);
                bl[ks][nb * 4 + 0] = t[0]; bl[ks][nb * 4 + 1] = t[1];
                bl[ks][nb * 4 + 2] = t[2]; bl[ks][nb * 4 + 3] = t[3];
            }
        }

        // ---- 96 MMAs, limb-major: consecutive MMAs never share an acc ----
#pragma unroll
        for (int ks = 0; ks < 2; ks++) {
            // pass 1: hi * hi
#pragma unroll
            for (int mf = 0; mf < 2; mf++)
#pragma unroll
                for (int nf = 0; nf < 4; nf++)
                    mma_bf16(acc[mf][nf], ah[ks][mf], bh[ks][nf * 2], bh[ks][nf * 2 + 1]);
            // pass 2: lo * hi
#pragma unroll
            for (int mf = 0; mf < 2; mf++)
#pragma unroll
                for (int nf = 0; nf < 4; nf++)
                    mma_bf16(acc[mf][nf], al[ks][mf], bh[ks][nf * 2], bh[ks][nf * 2 + 1]);
            // pass 3: hi * lo
#pragma unroll
            for (int mf = 0; mf < 2; mf++)
#pragma unroll
                for (int nf = 0; nf < 4; nf++)
                    mma_bf16(acc[mf][nf], ah[ks][mf], bl[ks][nf * 2], bl[ks][nf * 2 + 1]);
        }
        st++; if (st >= NSTAGE) st = 0;
    }

    // epilogue: bias (+ReLU), fp32 stores, M-guarded
    float* Cz = C + (size_t)blockIdx.z * zStride;
    int g = lid >> 2, t4 = lid & 3;
#pragma unroll
    for (int mf = 0; mf < 2; mf++) {
        int row0 = mBase + wm * 32 + mf * 16 + g;
        int row1 = row0 + 8;
        float bv0 = (row0 < M) ? bias[row0] : 0.f;
        float bv1 = (row1 < M) ? bias[row1] : 0.f;
#pragma unroll
        for (int nf = 0; nf < 4; nf++) {
            int col = p0 + wn * 32 + nf * 8 + 2 * t4;
            float v0 = acc[mf][nf][0] + bv0;
            float v1 = acc[mf][nf][1] + bv0;
            float v2 = acc[mf][nf][2] + bv1;
            float v3 = acc[mf][nf][3] + bv1;
            if (doRelu) {
                v0 = fmaxf(v0, 0.f); v1 = fmaxf(v1, 0.f);
                v2 = fmaxf(v2, 0.f); v3 = fmaxf(v3, 0.f);
            }
            if (row0 < M) *(float2*)(Cz + (size_t)row0 * NSP + col) = make_float2(v0, v1);
            if (row1 < M) *(float2*)(Cz + (size_t)row1 * NSP + col) = make_float2(v2, v3);
        }
    }
}

// ===========================================================================
// Split-K combine (offset path): C = P0 + P1 + bias
// ===========================================================================
__global__ __launch_bounds__(256) void combine_kernel(
    const float* __restrict__ P0, const float* __restrict__ P1,
    const float* __restrict__ bias, float* __restrict__ C, int total4)
{
    int i = blockIdx.x * 256 + threadIdx.x;
    if (i >= total4) return;
    int row = i / (NSP / 4);
    float bv = bias[row];
    float4 a = ((const float4*)P0)[i];
    float4 b = ((const float4*)P1)[i];
    float4 r;
    r.x = a.x + b.x + bv; r.y = a.y + b.y + bv;
    r.z = a.z + b.z + bv; r.w = a.w + b.w + bv;
    ((float4*)C)[i] = r;
}

// ===========================================================================
// Driver
// ===========================================================================
extern "C" void kernel_launch(void* const* d_in, const int* in_sizes, int n_in,
                              void* d_out, int out_size) {
    (void)in_sizes; (void)n_in; (void)out_size;
    const float* x = (const float*)d_in[0];
    const float* ow[4] = { (const float*)d_in[1], (const float*)d_in[5],
                           (const float*)d_in[9], (const float*)d_in[13] };
    const float* ob[4] = { (const float*)d_in[2], (const float*)d_in[6],
                           (const float*)d_in[10], (const float*)d_in[14] };
    const float* w[4]  = { (const float*)d_in[3], (const float*)d_in[7],
                           (const float*)d_in[11], (const float*)d_in[15] };
    const float* b[4]  = { (const float*)d_in[4], (const float*)d_in[8],
                           (const float*)d_in[12], (const float*)d_in[16] };
    float* out = (float*)d_out;

    __nv_bfloat16 *Shi, *Slo, *Whi, *Wlo, *OWhi, *OWlo;
    float *dbuf, *hbuf, *dp, *zb;
    cudaGetSymbolAddress((void**)&Shi,  g_Shi);
    cudaGetSymbolAddress((void**)&Slo,  g_Slo);
    cudaGetSymbolAddress((void**)&Whi,  g_Whi);
    cudaGetSymbolAddress((void**)&Wlo,  g_Wlo);
    cudaGetSymbolAddress((void**)&OWhi, g_OWhi);
    cudaGetSymbolAddress((void**)&OWlo, g_OWlo);
    cudaGetSymbolAddress((void**)&dbuf, g_d);
    cudaGetSymbolAddress((void**)&hbuf, g_h);
    cudaGetSymbolAddress((void**)&dp,   g_dp);
    cudaGetSymbolAddress((void**)&zb,   g_zerobias);
    float* h0 = hbuf;
    float* h1 = hbuf + (size_t)CIN * NSP;

    static int smemSet = 0;
    if (!smemSet) {
        cudaFuncSetAttribute(mma_gemm, cudaFuncAttributeMaxDynamicSharedMemorySize, SMTOT);
        smemSet = 1;
    }

    dim3 im2colGrid(NSP / 256, K27, CIN);
    dim3 sampleGrid(NSP / 128, K27);
    dim3 offGrid(NSP / 64, 1, 2);            // 128 x 1 x splitK2 = 256 CTAs
    dim3 mainGrid(NSP / 64, 2, 1);           // 128 x 2 = 256 CTAs
    int wN = CIN * CK;
    int wBlocks  = (wN + 255) / 256;
    int owBlocks = (128 * CK + 255) / 256;
    int offTot4 = 108 * NSP / 4;
    int offCombBlocks = (offTot4 + 255) / 256;

    const float* in = x;
    for (int L = 0; L < 3; L++) {
        split_kernel<<<wBlocks, 256>>>(w[L], Whi, Wlo, wN);
        owsplit_kernel<<<owBlocks, 256>>>(ow[L], OWhi, OWlo);
        im2col_split_kernel<<<im2colGrid, 256>>>(in, Shi, Slo);
        mma_gemm<<<offGrid, 256, SMTOT>>>(OWhi, OWlo, Shi, Slo, zb, dp,
                                          108, 108, 0, 108 * NSP);
        combine_kernel<<<offCombBlocks, 256>>>(dp, dp + (size_t)108 * NSP,
                                               ob[L], dbuf, offTot4);
        sample_kernel<<<sampleGrid, 128>>>(in, dbuf, Shi, Slo);
        float* hn = (L & 1) ? h1 : h0;
        mma_gemm<<<mainGrid, 256, SMTOT>>>(Whi, Wlo, Shi, Slo, b[L], hn,
                                           256, 216, 1, 0);
        in = hn;
    }
    // final: offsets from conv(h3), deformable conv applied to ORIGINAL x, no ReLU
    split_kernel<<<wBlocks, 256>>>(w[3], Whi, Wlo, wN);
    owsplit_kernel<<<owBlocks, 256>>>(ow[3], OWhi, OWlo);
    im2col_split_kernel<<<im2colGrid, 256>>>(in, Shi, Slo);
    mma_gemm<<<offGrid, 256, SMTOT>>>(OWhi, OWlo, Shi, Slo, zb, dp,
                                      108, 108, 0, 108 * NSP);
    combine_kernel<<<offCombBlocks, 256>>>(dp, dp + (size_t)108 * NSP,
                                           ob[3], dbuf, offTot4);
    sample_kernel<<<sampleGrid, 128>>>(x, dbuf, Shi, Slo);
    mma_gemm<<<mainGrid, 256, SMTOT>>>(Whi, Wlo, Shi, Slo, b[3], out,
                                       256, 216, 0, 0);
}

// round 16
// speedup vs baseline: 1.5004x; 1.5004x over previous
#include <cuda_runtime.h>
#include <cuda_bf16.h>
#include <math.h>
#include <stdint.h>

// Problem constants
#define NSP   8192          // D*H*W = 8*32*32
#define CIN   256
#define K27   27
#define CK    6912          // CIN * 27
#define DD    8
#define HH    32
#define WW    32

typedef unsigned long long ull;

// Scratch (allocation-free rule: __device__ globals)
__device__ float g_d[108 * NSP];                    // offset-conv output
__device__ float g_h[2][CIN * NSP];                 // hidden ping-pong
__device__ float g_dp[2][108 * NSP];                // split-K partials (offset conv)
__device__ float g_zerobias[256];                   // zero bias for partial passes
__device__ __nv_bfloat16 g_Shi[(size_t)CK * NSP];   // im2col/sampled matrix hi limb
__device__ __nv_bfloat16 g_Slo[(size_t)CK * NSP];   // im2col/sampled matrix lo limb
__device__ __nv_bfloat16 g_Whi[(size_t)CIN * CK];   // main weights hi limb
__device__ __nv_bfloat16 g_Wlo[(size_t)CIN * CK];   // main weights lo limb
__device__ __nv_bfloat16 g_OWhi[(size_t)128 * CK];  // offset weights hi (padded to 128 rows)
__device__ __nv_bfloat16 g_OWlo[(size_t)128 * CK];  // offset weights lo

// ===========================================================================
// PTX helpers
// ===========================================================================
__device__ __forceinline__ uint32_t smem_u32(const void* p) {
    uint32_t a;
    asm("{ .reg .u64 t; cvta.to.shared.u64 t, %1; cvt.u32.u64 %0, t; }" : "=r"(a) : "l"(p));
    return a;
}
__device__ __forceinline__ void cp16(uint32_t dst, const void* src) {
    asm volatile("cp.async.cg.shared.global [%0], [%1], 16;" :: "r"(dst), "l"(src));
}
__device__ __forceinline__ void cp_commit() {
    asm volatile("cp.async.commit_group;" ::: "memory");
}
template <int N>
__device__ __forceinline__ void cp_wait() {
    asm volatile("cp.async.wait_group %0;" :: "n"(N) : "memory");
}
__device__ __forceinline__ void ldsm4(uint32_t* r, uint32_t addr) {
    asm volatile("ldmatrix.sync.aligned.m8n8.x4.shared.b16 {%0,%1,%2,%3}, [%4];"
                 : "=r"(r[0]), "=r"(r[1]), "=r"(r[2]), "=r"(r[3]) : "r"(addr));
}
__device__ __forceinline__ void ldsm4t(uint32_t* r, uint32_t addr) {
    asm volatile("ldmatrix.sync.aligned.m8n8.x4.trans.shared.b16 {%0,%1,%2,%3}, [%4];"
                 : "=r"(r[0]), "=r"(r[1]), "=r"(r[2]), "=r"(r[3]) : "r"(addr));
}
__device__ __forceinline__ void mma_bf16(float* d, const uint32_t* a, uint32_t b0, uint32_t b1) {
    asm volatile("mma.sync.aligned.m16n8k16.row.col.f32.bf16.bf16.f32 "
                 "{%0,%1,%2,%3}, {%4,%5,%6,%7}, {%8,%9}, {%0,%1,%2,%3};"
                 : "+f"(d[0]), "+f"(d[1]), "+f"(d[2]), "+f"(d[3])
                 : "r"(a[0]), "r"(a[1]), "r"(a[2]), "r"(a[3]), "r"(b0), "r"(b1));
}

// ===========================================================================
// Weight limb-split: fp32 -> (hi, lo) bf16
// ===========================================================================
__global__ __launch_bounds__(256) void split_kernel(
    const float* __restrict__ src, __nv_bfloat16* __restrict__ hi,
    __nv_bfloat16* __restrict__ lo, int n)
{
    int i = blockIdx.x * 256 + threadIdx.x;
    if (i >= n) return;
    float a = src[i];
    __nv_bfloat16 h = __float2bfloat16(a);
    hi[i] = h;
    lo[i] = __float2bfloat16(a - __bfloat162float(h));
}

// Padded variant: 128 rows, rows >= 108 are zero.
__global__ __launch_bounds__(256) void owsplit_kernel(
    const float* __restrict__ src, __nv_bfloat16* __restrict__ hi,
    __nv_bfloat16* __restrict__ lo)
{
    int i = blockIdx.x * 256 + threadIdx.x;
    if (i >= 128 * CK) return;
    int row = i / CK;
    float a = (row < 108) ? src[i] : 0.0f;
    __nv_bfloat16 h = __float2bfloat16(a);
    hi[i] = h;
    lo[i] = __float2bfloat16(a - __bfloat162float(h));
}

// ===========================================================================
// Fused im2col + limb split for the plain 3x3x3 pad-1 conv
// ===========================================================================
__global__ __launch_bounds__(256) void im2col_split_kernel(
    const float* __restrict__ src,
    __nv_bfloat16* __restrict__ Shi, __nv_bfloat16* __restrict__ Slo)
{
    int p = blockIdx.x * 256 + threadIdx.x;   // grid.x = 32
    int k = blockIdx.y;                        // 27
    int c = blockIdx.z;                        // 256
    int z = p >> 10, y = (p >> 5) & 31, x = p & 31;
    int kd = k / 9, kh = (k / 3) % 3, kw = k % 3;
    int zz = z + kd - 1, yy = y + kh - 1, xx = x + kw - 1;
    float v = 0.0f;
    if ((unsigned)zz < DD && (unsigned)yy < HH && (unsigned)xx < WW)
        v = src[c * NSP + (zz << 10) + (yy << 5) + xx];
    __nv_bfloat16 hv = __float2bfloat16(v);
    size_t o = (size_t)(c * K27 + k) * NSP + p;
    Shi[o] = hv;
    Slo[o] = __float2bfloat16(v - __bfloat162float(hv));
}

// ===========================================================================
// Deformable sampling -> bf16 limb-split S  (S[(c*27+k)][p])
// ===========================================================================
__global__ void sample_kernel(const float* __restrict__ src,
                              const float* __restrict__ dd,
                              __nv_bfloat16* __restrict__ Shi,
                              __nv_bfloat16* __restrict__ Slo) {
    int p = blockIdx.x * 128 + threadIdx.x;   // grid.x = 64
    int k = blockIdx.y;                        // 27
    int z = p >> 10, y = (p >> 5) & 31, x = p & 31;
    int kd = k / 9, kh = (k / 3) % 3, kw = k % 3;

    float cd = (float)(z + kd - 1) + dd[(k * 3 + 0) * NSP + p];
    float ch = (float)(y + kh - 1) + dd[(k * 3 + 1) * NSP + p];
    float cw = (float)(x + kw - 1) + dd[(k * 3 + 2) * NSP + p];
    float m  = 1.0f / (1.0f + expf(-dd[(81 + k) * NSP + p]));

    float d0 = floorf(cd), h0 = floorf(ch), w0 = floorf(cw);
    float fd = cd - d0, fh = ch - h0, fw = cw - w0;
    int z0 = (int)d0, y0 = (int)h0, x0 = (int)w0;

    float wt[8]; int idx[8];
#pragma unroll
    for (int j = 0; j < 8; j++) {
        int dz = (j >> 2) & 1, dy = (j >> 1) & 1, dx = j & 1;
        int zi = z0 + dz, yi = y0 + dy, xi = x0 + dx;
        float w = (dz ? fd : 1.0f - fd) * (dy ? fh : 1.0f - fh) * (dx ? fw : 1.0f - fw);
        bool valid = ((unsigned)zi < DD) && ((unsigned)yi < HH) && ((unsigned)xi < WW);
        wt[j] = valid ? (w * m) : 0.0f;
        int zc = min(max(zi, 0), DD - 1);
        int yc = min(max(yi, 0), HH - 1);
        int xc = min(max(xi, 0), WW - 1);
        idx[j] = (zc << 10) + (yc << 5) + xc;
    }

    size_t base = (size_t)k * NSP + p;
#pragma unroll 4
    for (int c = 0; c < CIN; c++) {
        const float* b = src + c * NSP;
        float acc = wt[0] * b[idx[0]] + wt[1] * b[idx[1]]
                  + wt[2] * b[idx[2]] + wt[3] * b[idx[3]]
                  + wt[4] * b[idx[4]] + wt[5] * b[idx[5]]
                  + wt[6] * b[idx[6]] + wt[7] * b[idx[7]];
        __nv_bfloat16 hv = __float2bfloat16(acc);
        size_t o = base + (size_t)c * K27 * NSP;
        Shi[o] = hv;
        Slo[o] = __float2bfloat16(acc - __bfloat162float(hv));
    }
}

// ===========================================================================
// Tensor-core GEMM (mma.sync bf16, 2-limb split), 3-stage cp.async pipeline.
// Per-ks fragment loading (R13 register footprint), but MMAs in limb-major
// order within each ks: 3 passes of 8 accumulator-independent MMAs.
// ===========================================================================
#define ASZ   (128 * 40 * 2)      // 10240 B per A limb tile
#define BSZ   (32 * 72 * 2)       // 4608 B per B limb tile
#define STAGE (2 * ASZ + 2 * BSZ) // 29696 B
#define NSTAGE 3
#define SMTOT (NSTAGE * STAGE)    // 89088 B

__global__ __launch_bounds__(256) void mma_gemm(
    const __nv_bfloat16* __restrict__ Ahi, const __nv_bfloat16* __restrict__ Alo,
    const __nv_bfloat16* __restrict__ Bhi, const __nv_bfloat16* __restrict__ Blo,
    const float* __restrict__ bias, float* __restrict__ C,
    int M, int nkt, int doRelu, int zStride)
{
    extern __shared__ char smem[];
    uint32_t sb = smem_u32(smem);
    int tid = threadIdx.x;
    int wid = tid >> 5, lid = tid & 31;
    int p0 = blockIdx.x * 64;          // N tile base
    int mBase = blockIdx.y * 128;      // M tile base
    int ktBase = blockIdx.z * nkt;     // K-slice base (in BK=32 units)

    int wm = wid & 3;                  // 0..3 -> 32 rows each
    int wn = wid >> 2;                 // 0..1 -> 32 cols each
    int quad = lid >> 3, rr = lid & 7;

    // loader indices
    int aRow = tid >> 2;               // 0..63 (x2 with +64)
    int aU   = tid & 3;                // 16B unit in 64B row
    int bRow = tid >> 3;               // 0..31
    int bU   = tid & 7;                // 16B unit in 128B row

    float acc[2][4][4];
#pragma unroll
    for (int i = 0; i < 2; i++)
#pragma unroll
        for (int j = 0; j < 4; j++)
#pragma unroll
            for (int q = 0; q < 4; q++) acc[i][j][q] = 0.f;

    auto issue = [&](int st, int kt) {
        uint32_t s = sb + st * STAGE;
        int kOff = (ktBase + kt) * 32;
#pragma unroll
        for (int t = 0; t < 2; t++) {
            int row = aRow + t * 64;
            uint32_t d = s + row * 80 + aU * 16;
            const __nv_bfloat16* sh = Ahi + (size_t)(mBase + row) * CK + kOff + aU * 8;
            const __nv_bfloat16* sl = Alo + (size_t)(mBase + row) * CK + kOff + aU * 8;
            cp16(d, sh);
            cp16(d + ASZ, sl);
        }
        {
            uint32_t d = s + 2 * ASZ + bRow * 144 + bU * 16;
            const __nv_bfloat16* sh = Bhi + (size_t)(kOff + bRow) * NSP + p0 + bU * 8;
            const __nv_bfloat16* sl = Blo + (size_t)(kOff + bRow) * NSP + p0 + bU * 8;
            cp16(d, sh);
            cp16(d + BSZ, sl);
        }
        cp_commit();
    };

    // preload stages 0 and 1
    issue(0, 0);
    if (nkt > 1) issue(1, 1);

    int st = 0;
    for (int kt = 0; kt < nkt; kt++) {
        cp_wait<1>();          // stage for kt has landed
        __syncthreads();       // publish stage kt; fence vs new issue below

        if (kt + 2 < nkt) {
            int nst = st + 2; if (nst >= NSTAGE) nst -= NSTAGE;
            issue(nst, kt + 2);    // writes the stage freed at iteration kt-1
        }

        uint32_t s = sb + st * STAGE;
#pragma unroll
        for (int ks = 0; ks < 2; ks++) {
            int k0 = ks * 16;
            uint32_t ah[2][4], al[2][4];
#pragma unroll
            for (int mf = 0; mf < 2; mf++) {
                int row = wm * 32 + mf * 16 + ((quad & 1) ? 8 : 0) + rr;
                int col = k0 + ((quad >> 1) ? 8 : 0);
                uint32_t ad = s + (uint32_t)(row * 40 + col) * 2;
                ldsm4(ah[mf], ad);
                ldsm4(al[mf], ad + ASZ);
            }
            uint32_t bh[8], bl[8];
#pragma unroll
            for (int nb = 0; nb < 2; nb++) {
                int row = k0 + ((quad & 1) ? 8 : 0) + rr;
                int col = wn * 32 + nb * 16 + ((quad >> 1) ? 8 : 0);
                uint32_t bd = s + 2 * ASZ + (uint32_t)(row * 72 + col) * 2;
                uint32_t t[4];
                ldsm4t(t, bd);
                bh[nb * 4 + 0] = t[0]; bh[nb * 4 + 1] = t[1];
                bh[nb * 4 + 2] = t[2]; bh[nb * 4 + 3] = t[3];
                ldsm4t(t, bd + BSZ);
                bl[nb * 4 + 0] = t[0]; bl[nb * 4 + 1] = t[1];
                bl[nb * 4 + 2] = t[2]; bl[nb * 4 + 3] = t[3];
            }
            // limb-major: 3 passes of 8 accumulator-independent MMAs
#pragma unroll
            for (int mf = 0; mf < 2; mf++)
#pragma unroll
                for (int nf = 0; nf < 4; nf++)
                    mma_bf16(acc[mf][nf], ah[mf], bh[nf * 2], bh[nf * 2 + 1]);
#pragma unroll
            for (int mf = 0; mf < 2; mf++)
#pragma unroll
                for (int nf = 0; nf < 4; nf++)
                    mma_bf16(acc[mf][nf], al[mf], bh[nf * 2], bh[nf * 2 + 1]);
#pragma unroll
            for (int mf = 0; mf < 2; mf++)
#pragma unroll
                for (int nf = 0; nf < 4; nf++)
                    mma_bf16(acc[mf][nf], ah[mf], bl[nf * 2], bl[nf * 2 + 1]);
        }
        st++; if (st >= NSTAGE) st = 0;
    }

    // epilogue: bias (+ReLU), fp32 stores, M-guarded
    float* Cz = C + (size_t)blockIdx.z * zStride;
    int g = lid >> 2, t4 = lid & 3;
#pragma unroll
    for (int mf = 0; mf < 2; mf++) {
        int row0 = mBase + wm * 32 + mf * 16 + g;
        int row1 = row0 + 8;
        float bv0 = (row0 < M) ? bias[row0] : 0.f;
        float bv1 = (row1 < M) ? bias[row1] : 0.f;
#pragma unroll
        for (int nf = 0; nf < 4; nf++) {
            int col = p0 + wn * 32 + nf * 8 + 2 * t4;
            float v0 = acc[mf][nf][0] + bv0;
            float v1 = acc[mf][nf][1] + bv0;
            float v2 = acc[mf][nf][2] + bv1;
            float v3 = acc[mf][nf][3] + bv1;
            if (doRelu) {
                v0 = fmaxf(v0, 0.f); v1 = fmaxf(v1, 0.f);
                v2 = fmaxf(v2, 0.f); v3 = fmaxf(v3, 0.f);
            }
            if (row0 < M) *(float2*)(Cz + (size_t)row0 * NSP + col) = make_float2(v0, v1);
            if (row1 < M) *(float2*)(Cz + (size_t)row1 * NSP + col) = make_float2(v2, v3);
        }
    }
}

// ===========================================================================
// Split-K combine (offset path): C = P0 + P1 + bias
// ===========================================================================
__global__ __launch_bounds__(256) void combine_kernel(
    const float* __restrict__ P0, const float* __restrict__ P1,
    const float* __restrict__ bias, float* __restrict__ C, int total4)
{
    int i = blockIdx.x * 256 + threadIdx.x;
    if (i >= total4) return;
    int row = i / (NSP / 4);
    float bv = bias[row];
    float4 a = ((const float4*)P0)[i];
    float4 b = ((const float4*)P1)[i];
    float4 r;
    r.x = a.x + b.x + bv; r.y = a.y + b.y + bv;
    r.z = a.z + b.z + bv; r.w = a.w + b.w + bv;
    ((float4*)C)[i] = r;
}

// ===========================================================================
// Driver
// ===========================================================================
extern "C" void kernel_launch(void* const* d_in, const int* in_sizes, int n_in,
                              void* d_out, int out_size) {
    (void)in_sizes; (void)n_in; (void)out_size;
    const float* x = (const float*)d_in[0];
    const float* ow[4] = { (const float*)d_in[1], (const float*)d_in[5],
                           (const float*)d_in[9], (const float*)d_in[13] };
    const float* ob[4] = { (const float*)d_in[2], (const float*)d_in[6],
                           (const float*)d_in[10], (const float*)d_in[14] };
    const float* w[4]  = { (const float*)d_in[3], (const float*)d_in[7],
                           (const float*)d_in[11], (const float*)d_in[15] };
    const float* b[4]  = { (const float*)d_in[4], (const float*)d_in[8],
                           (const float*)d_in[12], (const float*)d_in[16] };
    float* out = (float*)d_out;

    __nv_bfloat16 *Shi, *Slo, *Whi, *Wlo, *OWhi, *OWlo;
    float *dbuf, *hbuf, *dp, *zb;
    cudaGetSymbolAddress((void**)&Shi,  g_Shi);
    cudaGetSymbolAddress((void**)&Slo,  g_Slo);
    cudaGetSymbolAddress((void**)&Whi,  g_Whi);
    cudaGetSymbolAddress((void**)&Wlo,  g_Wlo);
    cudaGetSymbolAddress((void**)&OWhi, g_OWhi);
    cudaGetSymbolAddress((void**)&OWlo, g_OWlo);
    cudaGetSymbolAddress((void**)&dbuf, g_d);
    cudaGetSymbolAddress((void**)&hbuf, g_h);
    cudaGetSymbolAddress((void**)&dp,   g_dp);
    cudaGetSymbolAddress((void**)&zb,   g_zerobias);
    float* h0 = hbuf;
    float* h1 = hbuf + (size_t)CIN * NSP;

    static int smemSet = 0;
    if (!smemSet) {
        cudaFuncSetAttribute(mma_gemm, cudaFuncAttributeMaxDynamicSharedMemorySize, SMTOT);
        smemSet = 1;
    }

    dim3 im2colGrid(NSP / 256, K27, CIN);
    dim3 sampleGrid(NSP / 128, K27);
    dim3 offGrid(NSP / 64, 1, 2);            // 128 x 1 x splitK2 = 256 CTAs
    dim3 mainGrid(NSP / 64, 2, 1);           // 128 x 2 = 256 CTAs
    int wN = CIN * CK;
    int wBlocks  = (wN + 255) / 256;
    int owBlocks = (128 * CK + 255) / 256;
    int offTot4 = 108 * NSP / 4;
    int offCombBlocks = (offTot4 + 255) / 256;

    const float* in = x;
    for (int L = 0; L < 3; L++) {
        split_kernel<<<wBlocks, 256>>>(w[L], Whi, Wlo, wN);
        owsplit_kernel<<<owBlocks, 256>>>(ow[L], OWhi, OWlo);
        im2col_split_kernel<<<im2colGrid, 256>>>(in, Shi, Slo);
        mma_gemm<<<offGrid, 256, SMTOT>>>(OWhi, OWlo, Shi, Slo, zb, dp,
                                          108, 108, 0, 108 * NSP);
        combine_kernel<<<offCombBlocks, 256>>>(dp, dp + (size_t)108 * NSP,
                                               ob[L], dbuf, offTot4);
        sample_kernel<<<sampleGrid, 128>>>(in, dbuf, Shi, Slo);
        float* hn = (L & 1) ? h1 : h0;
        mma_gemm<<<mainGrid, 256, SMTOT>>>(Whi, Wlo, Shi, Slo, b[L], hn,
                                           256, 216, 1, 0);
        in = hn;
    }
    // final: offsets from conv(h3), deformable conv applied to ORIGINAL x, no ReLU
    split_kernel<<<wBlocks, 256>>>(w[3], Whi, Wlo, wN);
    owsplit_kernel<<<owBlocks, 256>>>(ow[3], OWhi, OWlo);
    im2col_split_kernel<<<im2colGrid, 256>>>(in, Shi, Slo);
    mma_gemm<<<offGrid, 256, SMTOT>>>(OWhi, OWlo, Shi, Slo, zb, dp,
                                      108, 108, 0, 108 * NSP);
    combine_kernel<<<offCombBlocks, 256>>>(dp, dp + (size_t)108 * NSP,
                                           ob[3], dbuf, offTot4);
    sample_kernel<<<sampleGrid, 128>>>(x, dbuf, Shi, Slo);
    mma_gemm<<<mainGrid, 256, SMTOT>>>(Whi, Wlo, Shi, Slo, b[3], out,
                                       256, 216, 0, 0);
}